// round 16
// baseline (speedup 1.0000x reference)
#include <cuda_runtime.h>
#include <math.h>

// Problem constants (fixed by the dataset)
#define LL   4
#define BB   16
#define NN   4096
#define DD   1024
#define KK   20
#define KSEL 100
#define LD   (LL * DD)      // 4096, concatenated feature dim
#define NCH  8              // split-K chunks for Gram
#define KC   (LD / NCH)     // 512
#define KT   32             // k-tile within a chunk
#define NT   (KC / KT)      // 16 tiles
#define RS   106            // XsT row stride (floats), even for LDS.64 align
#define NBLK 55             // upper-triangle 10x10 blocks
#define PACK 5500           // packed floats per (b,chunk)
#define NCAND 1024          // candidate capacity for radix-select
#define NHIST 4096          // histogram buckets (top 12 bits)

// ---------------- scratch (static device globals; no allocation) ----------
__device__ int      g_topidx[BB * KSEL];
__device__ unsigned g_keys[BB * NN];                          // order-mapped scores
__device__ int      g_hist[BB * NHIST];                       // zero-init (BSS); select re-zeroes
__device__ float    g_A[(size_t)BB * KSEL * DD];              // layer-averaged tokens
__device__ float    g_Gpart[(size_t)BB * NCH * PACK];         // packed triangle partials

// kmeans init indices = jnp.linspace(0, 99, 20).astype(int32)
__constant__ int c_init[KK] = {0, 5, 10, 15, 20, 26, 31, 36, 41, 46,
                               52, 57, 62, 67, 72, 78, 83, 88, 93, 99};

// triangle block coords (I <= J), row-major over upper triangle
__constant__ int cbI[NBLK] = {0,0,0,0,0,0,0,0,0,0, 1,1,1,1,1,1,1,1,1,
                              2,2,2,2,2,2,2,2, 3,3,3,3,3,3,3, 4,4,4,4,4,4,
                              5,5,5,5,5, 6,6,6,6, 7,7,7, 8,8, 9};
__constant__ int cbJ[NBLK] = {0,1,2,3,4,5,6,7,8,9, 1,2,3,4,5,6,7,8,9,
                              2,3,4,5,6,7,8,9, 3,4,5,6,7,8,9, 4,5,6,7,8,9,
                              5,6,7,8,9, 6,7,8,9, 7,8,9, 8,9, 9};

// ---------------- K0: wide score kernel (128 CTAs) ------------------------
// Computes order-mapped keys for all (b,n) and builds the per-batch
// histogram with global atomics (counts deterministic regardless of order).
__global__ void __launch_bounds__(512) score_kernel(const float* __restrict__ am) {
    const int b = blockIdx.y;
    const int n = blockIdx.x * 512 + threadIdx.x;

    float s = 0.f;
#pragma unroll
    for (int l = 0; l < LL; l++) {
        const float2 p = *(const float2*)(am +
            ((size_t)((l * BB + b) * NN + n)) * 2);
        s += p.y - p.x;
    }
    unsigned u = __float_as_uint(s);
    u = (u & 0x80000000u) ? ~u : (u | 0x80000000u);  // order-preserving map
    g_keys[b * NN + n] = u;
    atomicAdd(&g_hist[b * NHIST + (u >> 20)], 1);
}

// ---------------- K1: narrow select (per-batch) ----------------------------
// Loads the 16KB hist slice to smem (re-zeroing global to keep the BSS
// zero-state invariant for graph replays), finds the threshold bucket,
// gathers candidates from g_keys, ranks by counting strictly-greater keys.
__global__ void __launch_bounds__(1024) score_select_kernel() {
    __shared__ int hist[NHIST];
    __shared__ unsigned long long cand[NCAND];
    __shared__ int cnt;
    __shared__ int Tsh;
    const int b   = blockIdx.x;
    const int tid = threadIdx.x;

    for (int h = tid; h < NHIST; h += 1024) {
        hist[h] = g_hist[b * NHIST + h];
        g_hist[b * NHIST + h] = 0;          // restore zero-state
    }
    if (tid == 0) cnt = 0;
    __syncthreads();

    // warp 0: scan buckets from the top until cumulative count >= 100
    if (tid < 32) {
        const int lane = tid;
        int run = 0, T = -1;
        for (int hi = NHIST - 32; hi >= 0 && T < 0; hi -= 32) {
            int c = hist[hi + lane];
            int s = c;
#pragma unroll
            for (int d = 1; d < 32; d <<= 1) {
                int v = __shfl_down_sync(0xFFFFFFFFu, s, d);
                if (lane + d < 32) s += v;
            }
            unsigned ball = __ballot_sync(0xFFFFFFFFu, run + s >= KSEL);
            if (ball) T = hi + (31 - __clz(ball));
            else      run += __shfl_sync(0xFFFFFFFFu, s, 0);
        }
        if (lane == 0) Tsh = T;
    }
    __syncthreads();
    const int T = Tsh;

    // gather candidates (keys unique -> ranking exact & deterministic)
    for (int n = tid; n < NN; n += 1024) {
        unsigned u = g_keys[b * NN + n];
        if ((int)(u >> 20) >= T) {
            int pos = atomicAdd(&cnt, 1);
            if (pos < NCAND)
                cand[pos] = ((unsigned long long)u << 32) |
                            (unsigned long long)(0xFFFFFFFFu - (unsigned)n);
        }
    }
    __syncthreads();

    // rank by counting strictly-greater keys; write winners directly
    const int C = (cnt < NCAND) ? cnt : NCAND;
    if (tid < C) {
        const unsigned long long mykey = cand[tid];
        int r = 0;
        for (int p = 0; p < C; p++)
            r += (cand[p] > mykey);
        if (r < KSEL)
            g_topidx[b * KSEL + r] =
                (int)(0xFFFFFFFFu - (unsigned)(mykey & 0xFFFFFFFFull));
    }
}

// ---------------- K2: symmetric Gram via triangle blocks + f32x2 ----------
// (R14 version verbatim: packed 55x100 output)
__global__ void __launch_bounds__(256) gram_kernel(const float* __restrict__ pt) {
    __shared__ __align__(16) float XsT[2][KT * RS];   // 27136 B, reused as red
    __shared__ unsigned rowoff[KSEL];
    const int ch  = blockIdx.x, b = blockIdx.y;
    const int tid = threadIdx.x;
    const int h   = tid >> 6;        // kk slice 0..3
    const int u   = tid & 63;        // in-slice id
    const bool comp = u < NBLK;
    const int bI  = (comp ? cbI[u] : 0) * 10;
    const int bJ  = (comp ? cbJ[u] : 0) * 10;

    if (tid < KSEL) {
        const int l = ch >> 1;
        const int doff = (ch & 1) * KC;
        int n = g_topidx[b * KSEL + tid];
        rowoff[tid] = (unsigned)((l * BB + b) * NN + n) * DD + doff;
    }
    __syncthreads();

    unsigned long long acc[10][5];
#pragma unroll
    for (int r = 0; r < 10; r++)
#pragma unroll
        for (int c = 0; c < 5; c++) acc[r][c] = 0ULL;

    float stage[13];
#pragma unroll
    for (int v = 0; v < 13; v++) {
        int e = tid + v * 256;
        if (e < KSEL * KT) stage[v] = pt[(size_t)rowoff[e >> 5] + (e & 31)];
    }

    for (int t = 0; t < NT; t++) {
        float* buf = XsT[t & 1];
#pragma unroll
        for (int v = 0; v < 13; v++) {
            int e = tid + v * 256;
            if (e < KSEL * KT) buf[(e & 31) * RS + (e >> 5)] = stage[v];
        }
        __syncthreads();

        if (t + 1 < NT) {
            const int koff = (t + 1) * KT;
#pragma unroll
            for (int v = 0; v < 13; v++) {
                int e = tid + v * 256;
                if (e < KSEL * KT)
                    stage[v] = pt[(size_t)rowoff[e >> 5] + koff + (e & 31)];
            }
        }

        if (comp) {
            const float* base = buf + (h * 8) * RS;
#pragma unroll
            for (int s = 0; s < 8; s++) {
                const float* row = base + s * RS;
                unsigned long long Av[5], Bv[5], Sp[10];
#pragma unroll
                for (int m = 0; m < 5; m++) {
                    Av[m] = *(const unsigned long long*)(row + bI + 2 * m);
                    Bv[m] = *(const unsigned long long*)(row + bJ + 2 * m);
                }
#pragma unroll
                for (int m = 0; m < 5; m++) {
                    unsigned lo = (unsigned)(Av[m] & 0xFFFFFFFFULL);
                    unsigned hi = (unsigned)(Av[m] >> 32);
                    asm("mov.b64 %0, {%1, %1};" : "=l"(Sp[2*m])   : "r"(lo));
                    asm("mov.b64 %0, {%1, %1};" : "=l"(Sp[2*m+1]) : "r"(hi));
                }
#pragma unroll
                for (int r = 0; r < 10; r++)
#pragma unroll
                    for (int c = 0; c < 5; c++)
                        asm("fma.rn.f32x2 %0, %1, %2, %0;"
                            : "+l"(acc[r][c]) : "l"(Sp[r]), "l"(Bv[c]));
            }
        }
    }
    __syncthreads();

    // deterministic cross-slice reduction into smem (ascending h)
    float* red = &XsT[0][0];
    for (int hh = 0; hh < 4; hh++) {
        if (h == hh && comp) {
            float* dst = red + u * 100;
#pragma unroll
            for (int r = 0; r < 10; r++)
#pragma unroll
                for (int c = 0; c < 5; c++) {
                    float lo = __uint_as_float((unsigned)(acc[r][c] & 0xFFFFFFFFULL));
                    float hi = __uint_as_float((unsigned)(acc[r][c] >> 32));
                    int o = r * 10 + 2 * c;
                    if (hh == 0) { dst[o] = lo; dst[o + 1] = hi; }
                    else         { dst[o] += lo; dst[o + 1] += hi; }
                }
        }
        __syncthreads();
    }

    float* Gp = g_Gpart + (size_t)(b * NCH + ch) * PACK;
    for (int e = tid; e < PACK; e += 256) Gp[e] = red[e];
}

// ---------------- K3: gather layer-averaged tokens A ----------------------
__global__ void gather_kernel(const float* __restrict__ pt) {
    const int i = blockIdx.x;
    const int b = blockIdx.y;
    const int tid = threadIdx.x;        // 256 threads, float4 over D=1024
    const int n = g_topidx[b * KSEL + i];
    const int d = tid * 4;

    float4 acc = make_float4(0.f, 0.f, 0.f, 0.f);
#pragma unroll
    for (int l = 0; l < LL; l++) {
        const float4 v = *(const float4*)(pt +
            (((size_t)(l * BB + b) * NN + n) * DD + d));
        acc.x += v.x; acc.y += v.y; acc.z += v.z; acc.w += v.w;
    }
    acc.x *= 0.25f; acc.y *= 0.25f; acc.z *= 0.25f; acc.w *= 0.25f;
    *(float4*)(g_A + ((size_t)(b * KSEL + i)) * DD + d) = acc;
}

// ---------------- K4: Lloyd kmeans (R11/R14 verbatim) ----------------------
__global__ void __launch_bounds__(1024) kmeans_kernel(float* __restrict__ out) {
    __shared__ float Gs[KSEL * KSEL];       // 40000 B (reused as partials)
    __shared__ float M[KK * KSEL];          //  8000 B (reused as coef)
    __shared__ float q[KK];
    __shared__ float invc[KK];
    __shared__ unsigned msk[KK * 4];
    __shared__ int start[KK + 1];
    __shared__ unsigned char labels[128];
    __shared__ unsigned char order[KSEL];
    const int b = blockIdx.x, tid = threadIdx.x;

    // packed split-K reduce (ascending chunks) + unpack + mirror
    for (int e4 = tid; e4 < PACK / 4; e4 += 1024) {
        float4 s = make_float4(0.f, 0.f, 0.f, 0.f);
#pragma unroll
        for (int ch = 0; ch < NCH; ch++) {
            const float4 v = ((const float4*)(g_Gpart +
                (size_t)(b * NCH + ch) * PACK))[e4];
            s.x += v.x; s.y += v.y; s.z += v.z; s.w += v.w;
        }
        const float vals[4] = {s.x, s.y, s.z, s.w};
#pragma unroll
        for (int k = 0; k < 4; k++) {
            int e  = e4 * 4 + k;
            int uu = e / 100;
            int w  = e - uu * 100;
            int i  = cbI[uu] * 10 + w / 10;
            int j  = cbJ[uu] * 10 + (w - (w / 10) * 10);
            Gs[i * KSEL + j] = vals[k];
            Gs[j * KSEL + i] = vals[k];
        }
    }
    if (tid >= KSEL && tid < 128) labels[tid] = 0xFF;   // ballot padding
    __syncthreads();

    if (tid < KK) {
        int p = c_init[tid];
        q[tid] = Gs[p * KSEL + p];
    }
    for (int e = tid; e < KK * KSEL; e += 1024) {
        int j = e / KSEL, i = e - j * KSEL;
        M[e] = Gs[c_init[j] * KSEL + i];
    }
    __syncthreads();

    const float gii = (tid < KSEL) ? Gs[tid * KSEL + tid] : 0.f;

    for (int t = 0; t <= 10; t++) {
        // --- assign: argmin_j (Gii - 2 M[j,i] + q[j]), first-min wins ---
        if (tid < KSEL) {
            float best = 3.4e38f;
            int   bj   = 0;
#pragma unroll
            for (int j = 0; j < KK; j++) {
                float d2 = gii - 2.f * M[j * KSEL + tid] + q[j];
                if (d2 < best) { best = d2; bj = j; }
            }
            labels[tid] = (unsigned char)bj;
        }
        __syncthreads();
        if (t == 10) break;

        // --- membership ballots: warps 0-3 cover points 0..127 ---
        if (tid < 128) {
            int lab = labels[tid];
            int w   = tid >> 5;
#pragma unroll
            for (int j = 0; j < KK; j++) {
                unsigned m = __ballot_sync(0xFFFFFFFFu, lab == j);
                if ((tid & 31) == 0) msk[j * 4 + w] = m;
            }
        }
        __syncthreads();

        // --- warp 0: counts, invc, exclusive scan -> start ---
        if (tid < 32) {
            int c = 0;
            if (tid < KK) {
                c = __popc(msk[tid * 4 + 0]) + __popc(msk[tid * 4 + 1])
                  + __popc(msk[tid * 4 + 2]) + __popc(msk[tid * 4 + 3]);
                invc[tid] = (c > 0) ? 1.f / (float)c : 0.f;
            }
            int s = c;
#pragma unroll
            for (int d = 1; d < 32; d <<= 1) {
                int v = __shfl_up_sync(0xFFFFFFFFu, s, d);
                if (tid >= d) s += v;
            }
            if (tid < KK) start[tid + 1] = s;
            if (tid == 0) start[0] = 0;
        }
        __syncthreads();

        // --- scatter: deterministic rank via masked popc ---
        if (tid < KSEL) {
            int lab = labels[tid];
            int w = tid >> 5, lane = tid & 31;
            int r = __popc(msk[lab * 4 + w] & ((1u << lane) - 1u));
            if (w > 0) r += __popc(msk[lab * 4 + 0]);
            if (w > 1) r += __popc(msk[lab * 4 + 1]);
            if (w > 2) r += __popc(msk[lab * 4 + 2]);
            order[start[lab] + r] = (unsigned char)tid;
        }
        __syncthreads();

        // --- M update: 1000 column-PAIRS, ascending-index segment sums ---
        if (tid < (KK * KSEL) / 2) {
            int j = tid / (KSEL / 2);
            int i = (tid - j * (KSEL / 2)) * 2;
            int s0 = start[j], s1 = start[j + 1];
            if (s1 > s0) {
                float sa = 0.f, sb = 0.f;
                for (int p = s0; p < s1; p++) {
                    const float2 v = *(const float2*)(Gs + (int)order[p] * KSEL + i);
                    sa += v.x; sb += v.y;
                }
                M[j * KSEL + i]     = sa * invc[j];
                M[j * KSEL + i + 1] = sb * invc[j];
            }
        }
        __syncthreads();

        // --- q update: warp per cluster, shuffle reduction ---
        {
            int w = tid >> 5, lane = tid & 31;
            if (w < KK) {
                int s0 = start[w], s1 = start[w + 1];
                float s = 0.f;
                for (int p = s0 + lane; p < s1; p += 32)
                    s += M[w * KSEL + (int)order[p]];
#pragma unroll
                for (int d = 16; d; d >>= 1)
                    s += __shfl_xor_sync(0xFFFFFFFFu, s, d);
                if (lane == 0 && s1 > s0) q[w] = s * invc[w];
            }
        }
        __syncthreads();
    }

    // ================= fused final epilogue (coalesced) =================
    if (tid < 128) {
        int lab = labels[tid];
        int w   = tid >> 5;
#pragma unroll
        for (int j = 0; j < KK; j++) {
            unsigned m = __ballot_sync(0xFFFFFFFFu, lab == j);
            if ((tid & 31) == 0) msk[j * 4 + w] = m;
        }
    }
    __syncthreads();
    if (tid < KK) {
        int c = __popc(msk[tid * 4 + 0]) + __popc(msk[tid * 4 + 1])
              + __popc(msk[tid * 4 + 2]) + __popc(msk[tid * 4 + 3]);
        invc[tid] = (c > 0) ? 1.f / (20.f * (float)c) : 0.f;
    }
    __syncthreads();

    float* coef = M;                 // reuse M
    if (tid < KSEL) coef[tid] = invc[labels[tid]];
    __syncthreads();

    const int g  = tid >> 8;         // 0..3
    const int dt = (tid & 255) * 4;  // float4 offset in D
    float4 acc = make_float4(0.f, 0.f, 0.f, 0.f);
    const float* Ab = g_A + (size_t)b * KSEL * DD;
#pragma unroll 5
    for (int i = g * 25; i < g * 25 + 25; i++) {
        float c = coef[i];
        const float4 v = *(const float4*)(Ab + (size_t)i * DD + dt);
        acc.x = fmaf(c, v.x, acc.x);
        acc.y = fmaf(c, v.y, acc.y);
        acc.z = fmaf(c, v.z, acc.z);
        acc.w = fmaf(c, v.w, acc.w);
    }
    __syncthreads();                 // Gs free from here
    ((float4*)Gs)[g * 256 + (tid & 255)] = acc;
    __syncthreads();

    if (tid < 256) {
        float4 s = make_float4(0.f, 0.f, 0.f, 0.f);
#pragma unroll
        for (int gg = 0; gg < 4; gg++) {
            const float4 v = ((const float4*)Gs)[gg * 256 + tid];
            s.x += v.x; s.y += v.y; s.z += v.z; s.w += v.w;
        }
        ((float4*)Gs)[1024 + tid] = s;
        float ss = s.x * s.x + s.y * s.y + s.z * s.z + s.w * s.w;
#pragma unroll
        for (int d = 16; d; d >>= 1) ss += __shfl_xor_sync(0xFFFFFFFFu, ss, d);
        if ((tid & 31) == 0) q[tid >> 5] = ss;
    }
    __syncthreads();
    if (tid == 0) {
        float v = 0.f;
#pragma unroll
        for (int w = 0; w < 8; w++) v += q[w];
        q[8] = 1.f / fmaxf(sqrtf(v), 1e-12f);
    }
    __syncthreads();
    if (tid < 256) {
        const float inv = q[8];
        float4 s = ((const float4*)Gs)[1024 + tid];
        float4 o = make_float4(s.x * inv, s.y * inv, s.z * inv, s.w * inv);
        *(float4*)(out + (size_t)b * DD + tid * 4) = o;
    }
}

// ---------------- launch ---------------------------------------------------
extern "C" void kernel_launch(void* const* d_in, const int* in_sizes, int n_in,
                              void* d_out, int out_size) {
    const float* pt = (const float*)d_in[0];   // patch_tokens [L,B,N,D] f32
    const float* am = (const float*)d_in[1];   // anomaly_maps [L,B,N,2] f32
    float* out = (float*)d_out;                // [B,D] f32

    score_kernel<<<dim3(NN / 512, BB), 512>>>(am);
    score_select_kernel<<<BB, 1024>>>();
    gram_kernel<<<dim3(NCH, BB), 256>>>(pt);
    gather_kernel<<<dim3(KSEL, BB), 256>>>(pt);
    kmeans_kernel<<<BB, 1024>>>(out);
}

// round 17
// speedup vs baseline: 1.1309x; 1.1309x over previous
#include <cuda_runtime.h>
#include <math.h>

// Problem constants (fixed by the dataset)
#define LL   4
#define BB   16
#define NN   4096
#define DD   1024
#define KK   20
#define KSEL 100
#define LD   (LL * DD)      // 4096, concatenated feature dim
#define NCH  8              // split-K chunks for Gram
#define KC   (LD / NCH)     // 512
#define KT   32             // k-tile within a chunk
#define NT   (KC / KT)      // 16 tiles
#define RS   106            // XsT row stride (floats), even for LDS.64 align
#define NBLK 55             // upper-triangle 10x10 blocks
#define PACK 5500           // packed floats per (b,chunk)
#define NCAND 1024          // candidate capacity for radix-select

// ---------------- scratch (static device globals; no allocation) ----------
__device__ int   g_topidx[BB * KSEL];
__device__ float g_A[(size_t)BB * KSEL * DD];                 // layer-averaged tokens
__device__ float g_Gpart[(size_t)BB * NCH * PACK];            // packed triangle partials

// kmeans init indices = jnp.linspace(0, 99, 20).astype(int32)
__constant__ int c_init[KK] = {0, 5, 10, 15, 20, 26, 31, 36, 41, 46,
                               52, 57, 62, 67, 72, 78, 83, 88, 93, 99};

// triangle block coords (I <= J), row-major over upper triangle
__constant__ int cbI[NBLK] = {0,0,0,0,0,0,0,0,0,0, 1,1,1,1,1,1,1,1,1,
                              2,2,2,2,2,2,2,2, 3,3,3,3,3,3,3, 4,4,4,4,4,4,
                              5,5,5,5,5, 6,6,6,6, 7,7,7, 8,8, 9};
__constant__ int cbJ[NBLK] = {0,1,2,3,4,5,6,7,8,9, 1,2,3,4,5,6,7,8,9,
                              2,3,4,5,6,7,8,9, 3,4,5,6,7,8,9, 4,5,6,7,8,9,
                              5,6,7,8,9, 6,7,8,9, 7,8,9, 8,9, 9};

// ---------------- K1: top-100 select (two-level scan + rank-by-count) -----
__global__ void __launch_bounds__(1024) score_select_kernel(const float* __restrict__ am) {
    __shared__ unsigned keys32[NN];
    __shared__ int hist[4096];
    __shared__ int csum[128];
    __shared__ unsigned long long cand[NCAND];
    __shared__ int cnt;
    __shared__ int Tsh;
    const int b   = blockIdx.x;
    const int tid = threadIdx.x;

    for (int h = tid; h < 4096; h += 1024) hist[h] = 0;
    if (tid == 0) cnt = 0;
    __syncthreads();

    for (int n = tid; n < NN; n += 1024) {
        float s = 0.f;
#pragma unroll
        for (int l = 0; l < LL; l++) {
            const float* p = am + ((size_t)((l * BB + b) * NN + n)) * 2;
            s += p[1] - p[0];
        }
        unsigned u = __float_as_uint(s);
        u = (u & 0x80000000u) ? ~u : (u | 0x80000000u);  // order-preserving map
        keys32[n] = u;
        atomicAdd(&hist[u >> 20], 1);
    }
    __syncthreads();

    // level 1: all 32 warps compute 128 chunk sums (chunk = 32 buckets)
    {
        const int w = tid >> 5, lane = tid & 31;
#pragma unroll
        for (int c = w; c < 128; c += 32) {
            int v = hist[c * 32 + lane];
#pragma unroll
            for (int d = 16; d; d >>= 1) v += __shfl_xor_sync(0xFFFFFFFFu, v, d);
            if (lane == 0) csum[c] = v;
        }
    }
    __syncthreads();

    // level 2: warp 0 scans chunk sums from the top, then refines in-chunk
    if (tid < 32) {
        const int lane = tid;
        int run = 0, TC = -1;
        for (int g = 128 - 32; g >= 0 && TC < 0; g -= 32) {
            int c = csum[g + lane];
            int s = c;
#pragma unroll
            for (int d = 1; d < 32; d <<= 1) {
                int v = __shfl_down_sync(0xFFFFFFFFu, s, d);
                if (lane + d < 32) s += v;
            }
            unsigned ball = __ballot_sync(0xFFFFFFFFu, run + s >= KSEL);
            if (ball) {
                int lamb = 31 - __clz(ball);
                TC = g + lamb;
                int sl = __shfl_sync(0xFFFFFFFFu, s, lamb);
                run += sl - csum[TC];      // cumulative strictly above chunk TC
            } else {
                run += __shfl_sync(0xFFFFFFFFu, s, 0);
            }
        }
        // refine within chunk TC
        int c2 = hist[TC * 32 + lane];
        int s2 = c2;
#pragma unroll
        for (int d = 1; d < 32; d <<= 1) {
            int v = __shfl_down_sync(0xFFFFFFFFu, s2, d);
            if (lane + d < 32) s2 += v;
        }
        unsigned ball2 = __ballot_sync(0xFFFFFFFFu, run + s2 >= KSEL);
        if (lane == 0) Tsh = TC * 32 + (31 - __clz(ball2));
    }
    __syncthreads();
    const int T = Tsh;

    // gather candidates (keys unique -> ranking exact & deterministic)
    for (int n = tid; n < NN; n += 1024) {
        unsigned u = keys32[n];
        if ((int)(u >> 20) >= T) {
            int pos = atomicAdd(&cnt, 1);
            if (pos < NCAND)
                cand[pos] = ((unsigned long long)u << 32) |
                            (unsigned long long)(0xFFFFFFFFu - (unsigned)n);
        }
    }
    __syncthreads();

    // rank by counting strictly-greater keys; write winners directly
    const int C = (cnt < NCAND) ? cnt : NCAND;
    if (tid < C) {
        const unsigned long long mykey = cand[tid];
        int r = 0;
        for (int p = 0; p < C; p++)
            r += (cand[p] > mykey);
        if (r < KSEL)
            g_topidx[b * KSEL + r] =
                (int)(0xFFFFFFFFu - (unsigned)(mykey & 0xFFFFFFFFull));
    }
}

// ---------------- K2: symmetric Gram via triangle blocks + f32x2 ----------
// (R14 version verbatim: packed 55x100 output)
__global__ void __launch_bounds__(256) gram_kernel(const float* __restrict__ pt) {
    __shared__ __align__(16) float XsT[2][KT * RS];   // 27136 B, reused as red
    __shared__ unsigned rowoff[KSEL];
    const int ch  = blockIdx.x, b = blockIdx.y;
    const int tid = threadIdx.x;
    const int h   = tid >> 6;        // kk slice 0..3
    const int u   = tid & 63;        // in-slice id
    const bool comp = u < NBLK;
    const int bI  = (comp ? cbI[u] : 0) * 10;
    const int bJ  = (comp ? cbJ[u] : 0) * 10;

    if (tid < KSEL) {
        const int l = ch >> 1;
        const int doff = (ch & 1) * KC;
        int n = g_topidx[b * KSEL + tid];
        rowoff[tid] = (unsigned)((l * BB + b) * NN + n) * DD + doff;
    }
    __syncthreads();

    unsigned long long acc[10][5];
#pragma unroll
    for (int r = 0; r < 10; r++)
#pragma unroll
        for (int c = 0; c < 5; c++) acc[r][c] = 0ULL;

    float stage[13];
#pragma unroll
    for (int v = 0; v < 13; v++) {
        int e = tid + v * 256;
        if (e < KSEL * KT) stage[v] = pt[(size_t)rowoff[e >> 5] + (e & 31)];
    }

    for (int t = 0; t < NT; t++) {
        float* buf = XsT[t & 1];
#pragma unroll
        for (int v = 0; v < 13; v++) {
            int e = tid + v * 256;
            if (e < KSEL * KT) buf[(e & 31) * RS + (e >> 5)] = stage[v];
        }
        __syncthreads();

        if (t + 1 < NT) {
            const int koff = (t + 1) * KT;
#pragma unroll
            for (int v = 0; v < 13; v++) {
                int e = tid + v * 256;
                if (e < KSEL * KT)
                    stage[v] = pt[(size_t)rowoff[e >> 5] + koff + (e & 31)];
            }
        }

        if (comp) {
            const float* base = buf + (h * 8) * RS;
#pragma unroll
            for (int s = 0; s < 8; s++) {
                const float* row = base + s * RS;
                unsigned long long Av[5], Bv[5], Sp[10];
#pragma unroll
                for (int m = 0; m < 5; m++) {
                    Av[m] = *(const unsigned long long*)(row + bI + 2 * m);
                    Bv[m] = *(const unsigned long long*)(row + bJ + 2 * m);
                }
#pragma unroll
                for (int m = 0; m < 5; m++) {
                    unsigned lo = (unsigned)(Av[m] & 0xFFFFFFFFULL);
                    unsigned hi = (unsigned)(Av[m] >> 32);
                    asm("mov.b64 %0, {%1, %1};" : "=l"(Sp[2*m])   : "r"(lo));
                    asm("mov.b64 %0, {%1, %1};" : "=l"(Sp[2*m+1]) : "r"(hi));
                }
#pragma unroll
                for (int r = 0; r < 10; r++)
#pragma unroll
                    for (int c = 0; c < 5; c++)
                        asm("fma.rn.f32x2 %0, %1, %2, %0;"
                            : "+l"(acc[r][c]) : "l"(Sp[r]), "l"(Bv[c]));
            }
        }
    }
    __syncthreads();

    // deterministic cross-slice reduction into smem (ascending h)
    float* red = &XsT[0][0];
    for (int hh = 0; hh < 4; hh++) {
        if (h == hh && comp) {
            float* dst = red + u * 100;
#pragma unroll
            for (int r = 0; r < 10; r++)
#pragma unroll
                for (int c = 0; c < 5; c++) {
                    float lo = __uint_as_float((unsigned)(acc[r][c] & 0xFFFFFFFFULL));
                    float hi = __uint_as_float((unsigned)(acc[r][c] >> 32));
                    int o = r * 10 + 2 * c;
                    if (hh == 0) { dst[o] = lo; dst[o + 1] = hi; }
                    else         { dst[o] += lo; dst[o + 1] += hi; }
                }
        }
        __syncthreads();
    }

    float* Gp = g_Gpart + (size_t)(b * NCH + ch) * PACK;
    for (int e = tid; e < PACK; e += 256) Gp[e] = red[e];
}

// ---------------- K3: gather A, 4 tokens/CTA, 16 outstanding loads --------
// Same arithmetic order as before per token: (((v0+v1)+v2)+v3)*0.25.
__global__ void __launch_bounds__(256) gather_kernel(const float* __restrict__ pt) {
    const int i0 = blockIdx.x * 4;      // tokens i0..i0+3
    const int b  = blockIdx.y;
    const int tid = threadIdx.x;        // 256 threads, float4 over D=1024
    const int d = tid * 4;

    int n[4];
#pragma unroll
    for (int t = 0; t < 4; t++) n[t] = g_topidx[b * KSEL + i0 + t];

    // issue all 16 independent loads
    float4 v[4][4];
#pragma unroll
    for (int t = 0; t < 4; t++)
#pragma unroll
        for (int l = 0; l < LL; l++)
            v[t][l] = *(const float4*)(pt +
                (((size_t)(l * BB + b) * NN + n[t]) * DD + d));

#pragma unroll
    for (int t = 0; t < 4; t++) {
        float4 acc = make_float4(0.f, 0.f, 0.f, 0.f);
#pragma unroll
        for (int l = 0; l < LL; l++) {
            acc.x += v[t][l].x; acc.y += v[t][l].y;
            acc.z += v[t][l].z; acc.w += v[t][l].w;
        }
        acc.x *= 0.25f; acc.y *= 0.25f; acc.z *= 0.25f; acc.w *= 0.25f;
        *(float4*)(g_A + ((size_t)(b * KSEL + i0 + t)) * DD + d) = acc;
    }
}

// ---------------- K4: Lloyd kmeans (R11/R14 verbatim) ----------------------
__global__ void __launch_bounds__(1024) kmeans_kernel(float* __restrict__ out) {
    __shared__ float Gs[KSEL * KSEL];       // 40000 B (reused as partials)
    __shared__ float M[KK * KSEL];          //  8000 B (reused as coef)
    __shared__ float q[KK];
    __shared__ float invc[KK];
    __shared__ unsigned msk[KK * 4];
    __shared__ int start[KK + 1];
    __shared__ unsigned char labels[128];
    __shared__ unsigned char order[KSEL];
    const int b = blockIdx.x, tid = threadIdx.x;

    // packed split-K reduce (ascending chunks) + unpack + mirror
    for (int e4 = tid; e4 < PACK / 4; e4 += 1024) {
        float4 s = make_float4(0.f, 0.f, 0.f, 0.f);
#pragma unroll
        for (int ch = 0; ch < NCH; ch++) {
            const float4 v = ((const float4*)(g_Gpart +
                (size_t)(b * NCH + ch) * PACK))[e4];
            s.x += v.x; s.y += v.y; s.z += v.z; s.w += v.w;
        }
        const float vals[4] = {s.x, s.y, s.z, s.w};
#pragma unroll
        for (int k = 0; k < 4; k++) {
            int e  = e4 * 4 + k;
            int uu = e / 100;
            int w  = e - uu * 100;
            int i  = cbI[uu] * 10 + w / 10;
            int j  = cbJ[uu] * 10 + (w - (w / 10) * 10);
            Gs[i * KSEL + j] = vals[k];
            Gs[j * KSEL + i] = vals[k];
        }
    }
    if (tid >= KSEL && tid < 128) labels[tid] = 0xFF;   // ballot padding
    __syncthreads();

    if (tid < KK) {
        int p = c_init[tid];
        q[tid] = Gs[p * KSEL + p];
    }
    for (int e = tid; e < KK * KSEL; e += 1024) {
        int j = e / KSEL, i = e - j * KSEL;
        M[e] = Gs[c_init[j] * KSEL + i];
    }
    __syncthreads();

    const float gii = (tid < KSEL) ? Gs[tid * KSEL + tid] : 0.f;

    for (int t = 0; t <= 10; t++) {
        // --- assign: argmin_j (Gii - 2 M[j,i] + q[j]), first-min wins ---
        if (tid < KSEL) {
            float best = 3.4e38f;
            int   bj   = 0;
#pragma unroll
            for (int j = 0; j < KK; j++) {
                float d2 = gii - 2.f * M[j * KSEL + tid] + q[j];
                if (d2 < best) { best = d2; bj = j; }
            }
            labels[tid] = (unsigned char)bj;
        }
        __syncthreads();
        if (t == 10) break;

        // --- membership ballots: warps 0-3 cover points 0..127 ---
        if (tid < 128) {
            int lab = labels[tid];
            int w   = tid >> 5;
#pragma unroll
            for (int j = 0; j < KK; j++) {
                unsigned m = __ballot_sync(0xFFFFFFFFu, lab == j);
                if ((tid & 31) == 0) msk[j * 4 + w] = m;
            }
        }
        __syncthreads();

        // --- warp 0: counts, invc, exclusive scan -> start ---
        if (tid < 32) {
            int c = 0;
            if (tid < KK) {
                c = __popc(msk[tid * 4 + 0]) + __popc(msk[tid * 4 + 1])
                  + __popc(msk[tid * 4 + 2]) + __popc(msk[tid * 4 + 3]);
                invc[tid] = (c > 0) ? 1.f / (float)c : 0.f;
            }
            int s = c;
#pragma unroll
            for (int d = 1; d < 32; d <<= 1) {
                int v = __shfl_up_sync(0xFFFFFFFFu, s, d);
                if (tid >= d) s += v;
            }
            if (tid < KK) start[tid + 1] = s;
            if (tid == 0) start[0] = 0;
        }
        __syncthreads();

        // --- scatter: deterministic rank via masked popc ---
        if (tid < KSEL) {
            int lab = labels[tid];
            int w = tid >> 5, lane = tid & 31;
            int r = __popc(msk[lab * 4 + w] & ((1u << lane) - 1u));
            if (w > 0) r += __popc(msk[lab * 4 + 0]);
            if (w > 1) r += __popc(msk[lab * 4 + 1]);
            if (w > 2) r += __popc(msk[lab * 4 + 2]);
            order[start[lab] + r] = (unsigned char)tid;
        }
        __syncthreads();

        // --- M update: 1000 column-PAIRS, ascending-index segment sums ---
        if (tid < (KK * KSEL) / 2) {
            int j = tid / (KSEL / 2);
            int i = (tid - j * (KSEL / 2)) * 2;
            int s0 = start[j], s1 = start[j + 1];
            if (s1 > s0) {
                float sa = 0.f, sb = 0.f;
                for (int p = s0; p < s1; p++) {
                    const float2 v = *(const float2*)(Gs + (int)order[p] * KSEL + i);
                    sa += v.x; sb += v.y;
                }
                M[j * KSEL + i]     = sa * invc[j];
                M[j * KSEL + i + 1] = sb * invc[j];
            }
        }
        __syncthreads();

        // --- q update: warp per cluster, shuffle reduction ---
        {
            int w = tid >> 5, lane = tid & 31;
            if (w < KK) {
                int s0 = start[w], s1 = start[w + 1];
                float s = 0.f;
                for (int p = s0 + lane; p < s1; p += 32)
                    s += M[w * KSEL + (int)order[p]];
#pragma unroll
                for (int d = 16; d; d >>= 1)
                    s += __shfl_xor_sync(0xFFFFFFFFu, s, d);
                if (lane == 0 && s1 > s0) q[w] = s * invc[w];
            }
        }
        __syncthreads();
    }

    // ================= fused final epilogue (coalesced) =================
    if (tid < 128) {
        int lab = labels[tid];
        int w   = tid >> 5;
#pragma unroll
        for (int j = 0; j < KK; j++) {
            unsigned m = __ballot_sync(0xFFFFFFFFu, lab == j);
            if ((tid & 31) == 0) msk[j * 4 + w] = m;
        }
    }
    __syncthreads();
    if (tid < KK) {
        int c = __popc(msk[tid * 4 + 0]) + __popc(msk[tid * 4 + 1])
              + __popc(msk[tid * 4 + 2]) + __popc(msk[tid * 4 + 3]);
        invc[tid] = (c > 0) ? 1.f / (20.f * (float)c) : 0.f;
    }
    __syncthreads();

    float* coef = M;                 // reuse M
    if (tid < KSEL) coef[tid] = invc[labels[tid]];
    __syncthreads();

    const int g  = tid >> 8;         // 0..3
    const int dt = (tid & 255) * 4;  // float4 offset in D
    float4 acc = make_float4(0.f, 0.f, 0.f, 0.f);
    const float* Ab = g_A + (size_t)b * KSEL * DD;
#pragma unroll 5
    for (int i = g * 25; i < g * 25 + 25; i++) {
        float c = coef[i];
        const float4 v = *(const float4*)(Ab + (size_t)i * DD + dt);
        acc.x = fmaf(c, v.x, acc.x);
        acc.y = fmaf(c, v.y, acc.y);
        acc.z = fmaf(c, v.z, acc.z);
        acc.w = fmaf(c, v.w, acc.w);
    }
    __syncthreads();                 // Gs free from here
    ((float4*)Gs)[g * 256 + (tid & 255)] = acc;
    __syncthreads();

    if (tid < 256) {
        float4 s = make_float4(0.f, 0.f, 0.f, 0.f);
#pragma unroll
        for (int gg = 0; gg < 4; gg++) {
            const float4 v = ((const float4*)Gs)[gg * 256 + tid];
            s.x += v.x; s.y += v.y; s.z += v.z; s.w += v.w;
        }
        ((float4*)Gs)[1024 + tid] = s;
        float ss = s.x * s.x + s.y * s.y + s.z * s.z + s.w * s.w;
#pragma unroll
        for (int d = 16; d; d >>= 1) ss += __shfl_xor_sync(0xFFFFFFFFu, ss, d);
        if ((tid & 31) == 0) q[tid >> 5] = ss;
    }
    __syncthreads();
    if (tid == 0) {
        float v = 0.f;
#pragma unroll
        for (int w = 0; w < 8; w++) v += q[w];
        q[8] = 1.f / fmaxf(sqrtf(v), 1e-12f);
    }
    __syncthreads();
    if (tid < 256) {
        const float inv = q[8];
        float4 s = ((const float4*)Gs)[1024 + tid];
        float4 o = make_float4(s.x * inv, s.y * inv, s.z * inv, s.w * inv);
        *(float4*)(out + (size_t)b * DD + tid * 4) = o;
    }
}

// ---------------- launch ---------------------------------------------------
extern "C" void kernel_launch(void* const* d_in, const int* in_sizes, int n_in,
                              void* d_out, int out_size) {
    const float* pt = (const float*)d_in[0];   // patch_tokens [L,B,N,D] f32
    const float* am = (const float*)d_in[1];   // anomaly_maps [L,B,N,2] f32
    float* out = (float*)d_out;                // [B,D] f32

    score_select_kernel<<<BB, 1024>>>(am);
    gram_kernel<<<dim3(NCH, BB), 256>>>(pt);
    gather_kernel<<<dim3(KSEL / 4, BB), 256>>>(pt);
    kmeans_kernel<<<BB, 1024>>>(out);
}